// round 16
// baseline (speedup 1.0000x reference)
#include <cuda_runtime.h>
#include <math.h>

static constexpr int B_DIM = 8192;
static constexpr int N_PTS = 1024;
static constexpr int THREADS = 256;
static constexpr int CTAS_PER_SM = 7;
static constexpr int GRID = 148 * CTAS_PER_SM;               // 1036, one full wave
static constexpr int MAX_ROWS = (B_DIM + GRID - 1) / GRID;   // 8 rows per CTA max

// Allocation-free scratch (__device__ globals per harness rules).
__device__ double g_acc;            // zero at load; self-reset by last block
__device__ unsigned int g_ticket;   // ditto

__device__ __forceinline__ float fast_sqrt(float x) {
    float r;
    asm("sqrt.approx.f32 %0, %1;" : "=f"(r) : "f"(x));
    return r;
}

__device__ __forceinline__ void euler_to_matrix(float a, float b, float c, float* R) {
    const float sa = sinf(a), ca = cosf(a);
    const float sb = sinf(b), cb = cosf(b);
    const float sc = sinf(c), cc = cosf(c);
    // R = Rx(a) * Ry(b) * Rz(c)
    R[0] = cb * cc;
    R[1] = -cb * sc;
    R[2] = sb;
    R[3] = ca * sc + sa * sb * cc;
    R[4] = ca * cc - sa * sb * sc;
    R[5] = -sa * cb;
    R[6] = sa * sc - ca * sb * cc;
    R[7] = sa * cc + ca * sb * sc;
    R[8] = ca * cb;
}

__device__ __forceinline__ void compute_D(int b,
                                          const float* __restrict__ pred,
                                          const float* __restrict__ mode,
                                          const float* __restrict__ gt,
                                          float* __restrict__ Dout /*12 floats*/) {
    const float m1 = pred[b * 4 + 0];
    const float m2 = pred[b * 4 + 1];
    const float m3 = pred[b * 4 + 2];
    const float m4 = pred[b * 4 + 3];
    const float sgn = (mode[b] > 0.5f) ? 1.0f : -1.0f;
    const float denom = m1 * m1 + m2 * m2 + m3 * m3;
    const float e2 = sgn * asinf(sqrtf(m3 * m3 / denom));
    const float se2 = sinf(e2);
    const float ce2 = cosf(e2);
    const float e3 = atan2f(m4, m3 / (se2 + 1e-9f));
    const float tmp = ce2 * cosf(e3);
    const float e1 = atan2f(m2 / tmp, m1 / tmp);
    // (ref's +2pi wrap of euler3 only shifts by a full period; sin/cos unchanged)

    float Rp[9], Rg[9];
    euler_to_matrix(e1, e2, e3, Rp);
    euler_to_matrix(gt[b * 3 + 0], gt[b * 3 + 1], gt[b * 3 + 2], Rg);
    #pragma unroll
    for (int i = 0; i < 9; i++) Dout[i] = Rp[i] - Rg[i];
    Dout[9] = Dout[10] = Dout[11] = 0.0f;
}

// Single fused persistent kernel (R14 structure + L2 prefetch of row 0 before
// the trig prologue + 7 CTAs/SM residency).
__global__ __launch_bounds__(THREADS, CTAS_PER_SM)
void add_loss_kernel(const float* __restrict__ pred,
                     const float* __restrict__ mode,
                     const float* __restrict__ gt,
                     const float* __restrict__ point,
                     float* __restrict__ out) {
    __shared__ float Dsh[MAX_ROWS][12];       // 48B rows, float4-aligned
    __shared__ float warp_sums[THREADS / 32];

    const int t = threadIdx.x;

    // Base pointer for this thread's first row segment.
    const float4* __restrict__ p = (const float4*)(point)
        + (size_t)blockIdx.x * (N_PTS * 3 / 4) + 3 * t;
    const size_t p_step = (size_t)GRID * (N_PTS * 3 / 4);

    // Warm L2 with row 0's data BEFORE the trig prologue so its DRAM latency
    // overlaps the ~1000-cycle trig chain instead of following it.
    asm volatile("prefetch.global.L2 [%0];" :: "l"(p + 0));
    asm volatile("prefetch.global.L2 [%0];" :: "l"(p + 1));
    asm volatile("prefetch.global.L2 [%0];" :: "l"(p + 2));

    // Distributed trig: one thread per row owned by this CTA, fully parallel,
    // once per CTA lifetime.
    if (t < MAX_ROWS) {
        const int b = blockIdx.x + t * GRID;
        if (b < B_DIM) compute_D(b, pred, mode, gt, Dsh[t]);
    }
    __syncthreads();

    float acc = 0.0f;
    int k = 0;
    #pragma unroll 1
    for (int b = blockIdx.x; b < B_DIM; b += GRID, p += p_step, k++) {
        // 3 point LDG.128 (the only global traffic in the loop).
        const float4 av = p[0];
        const float4 bv = p[1];
        const float4 cv = p[2];

        // D from shared: 3 broadcast LDS.128.
        const float4* Drow = (const float4*)Dsh[k];
        const float4 D0 = Drow[0];
        const float4 D1 = Drow[1];
        const float4 D2 = Drow[2];

        const float d00 = D0.x, d01 = D0.y, d02 = D0.z;
        const float d10 = D0.w, d11 = D1.x, d12 = D1.y;
        const float d20 = D1.z, d21 = D1.w, d22 = D2.x;

        const float px[4] = {av.x, av.w, bv.z, cv.y};
        const float py[4] = {av.y, bv.x, bv.w, cv.z};
        const float pz[4] = {av.z, bv.y, cv.x, cv.w};
        #pragma unroll
        for (int i = 0; i < 4; i++) {
            const float q0 = fmaf(px[i], d00, fmaf(py[i], d10, pz[i] * d20));
            const float q1 = fmaf(px[i], d01, fmaf(py[i], d11, pz[i] * d21));
            const float q2 = fmaf(px[i], d02, fmaf(py[i], d12, pz[i] * d22));
            acc += fast_sqrt(fmaf(q0, q0, fmaf(q1, q1, q2 * q2)));
        }
    }

    // One reduce + one atomic per CTA.
    #pragma unroll
    for (int off = 16; off > 0; off >>= 1)
        acc += __shfl_xor_sync(0xffffffffu, acc, off);
    if ((t & 31) == 0) warp_sums[t >> 5] = acc;
    __syncthreads();

    if (t == 0) {
        float s = 0.0f;
        #pragma unroll
        for (int w = 0; w < THREADS / 32; w++) s += warp_sums[w];
        atomicAdd(&g_acc, (double)s);
        __threadfence();
        const unsigned int ticket = atomicAdd(&g_ticket, 1u);
        if (ticket == (unsigned int)(gridDim.x - 1)) {
            __threadfence();
            const double total = atomicAdd(&g_acc, 0.0);
            out[0] = (float)(total * (1.0 / ((double)B_DIM * (double)N_PTS)));
            // Self-reset for next graph replay (stream-ordered after all atomics).
            g_acc = 0.0;
            g_ticket = 0u;
        }
    }
}

extern "C" void kernel_launch(void* const* d_in, const int* in_sizes, int n_in,
                              void* d_out, int out_size) {
    const float* pred  = (const float*)d_in[0];   // (8192, 4)
    const float* mode  = (const float*)d_in[1];   // (8192,)
    const float* gt    = (const float*)d_in[2];   // (8192, 3)
    const float* point = (const float*)d_in[3];   // (8192, 1024, 3)
    float* out = (float*)d_out;

    add_loss_kernel<<<GRID, THREADS>>>(pred, mode, gt, point, out);
}